// round 7
// baseline (speedup 1.0000x reference)
#include <cuda_runtime.h>
#include <math.h>

#define K_DIM   76800           // 3*160*160
#define NGROUP  19200           // groups of 4 columns
#define NBATCH  1024
#define NOUT    8
#define THREADS 768
#define WARPS   24
#define ROWS    2
#define CPW     25              // chunks per warp: 600 chunks / 24 warps
#define D1      8               // pass-1 ring depth (512B stages)
#define D2      4               // pass-2 W ring depth (1KB stages)
#define EPS_F   1e-5f
#define MAGIC   12582912.0f     // 2^23 + 2^22

// ---------------- device scratch ----------------
#define MEAN_BLKS 512
__device__ float  g_mp[MEAN_BLKS];
__device__ float  g_wscale;               // fl(1/clip(mean|W|,eps))
__device__ float  g_c;                    // tf32(fl(1/g_wscale))
__device__ int    g_wpack[NGROUP * NOUT]; // packed ternary weights (s8 x4)

// ---------------- ptx helpers ----------------
__device__ __forceinline__ float tf32_rna(float x) {
    unsigned u;
    asm("cvt.rna.tf32.f32 %0, %1;" : "=r"(u) : "f"(x));
    return __uint_as_float(u);
}
__device__ __forceinline__ int dp4a_ss(unsigned a, int b, int c) {
    asm("dp4a.s32.s32 %0, %1, %2, %3;" : "=r"(c) : "r"(a), "r"(b), "r"(c));
    return c;
}
__device__ __forceinline__ int dp2a_lo_us(unsigned a, int b, int c) {
    asm("dp2a.lo.u32.s32 %0, %1, %2, %3;" : "=r"(c) : "r"(a), "r"(b), "r"(c));
    return c;
}
__device__ __forceinline__ int dp2a_hi_us(unsigned a, int b, int c) {
    asm("dp2a.hi.u32.s32 %0, %1, %2, %3;" : "=r"(c) : "r"(a), "r"(b), "r"(c));
    return c;
}
__device__ __forceinline__ unsigned prmt(unsigned a, unsigned b, unsigned s) {
    unsigned d;
    asm("prmt.b32 %0, %1, %2, %3;" : "=r"(d) : "r"(a), "r"(b), "r"(s));
    return d;
}
__device__ __forceinline__ void cp_async16(void* dst_smem, const void* src_glob) {
    unsigned d = (unsigned)__cvta_generic_to_shared(dst_smem);
    asm volatile("cp.async.cg.shared.global [%0], [%1], 16;"
                 :: "r"(d), "l"(src_glob) : "memory");
}
#define CP_COMMIT() asm volatile("cp.async.commit_group;" ::: "memory")
#define CP_WAIT(n)  asm volatile("cp.async.wait_group %0;" :: "n"(n) : "memory")

// ---------------- W pipeline ----------------
__global__ void wmean_kernel(const float* __restrict__ W) {
    // fp32 per-thread (<=8 values) + fp32 block tree: no FP64 on hot path
    const float4* W4 = (const float4*)W;
    const int n4 = NOUT * K_DIM / 4;   // 153600
    float s = 0.f;
    for (int i = blockIdx.x * blockDim.x + threadIdx.x; i < n4;
         i += gridDim.x * blockDim.x) {
        float4 v = W4[i];
        s += ((fabsf(v.x) + fabsf(v.y)) + (fabsf(v.z) + fabsf(v.w)));
    }
    __shared__ float sh[256];
    sh[threadIdx.x] = s;
    __syncthreads();
    for (int off = 128; off > 0; off >>= 1) {
        if (threadIdx.x < off) sh[threadIdx.x] += sh[threadIdx.x + off];
        __syncthreads();
    }
    if (threadIdx.x == 0) g_mp[blockIdx.x] = sh[0];
}

// folds the final mean-reduction in (every block redundantly reduces g_mp)
__global__ void wpack_kernel(const float* __restrict__ W) {
    __shared__ double sh[256];
    __shared__ float s_wsc;
    int t = threadIdx.x;
    sh[t] = (double)g_mp[t] + (double)g_mp[t + 256];
    __syncthreads();
    for (int off = 128; off > 0; off >>= 1) {
        if (t < off) sh[t] += sh[t + off];
        __syncthreads();
    }
    if (t == 0) {
        float sumf = (float)sh[0];
        float mean = __fdiv_rn(sumf, (float)(NOUT * K_DIM));
        float mcl  = fmaxf(mean, EPS_F);
        float wsc  = __fdiv_rn(1.0f, mcl);
        s_wsc = wsc;
        if (blockIdx.x == 0) {
            g_wscale = wsc;
            g_c = tf32_rna(__fdiv_rn(1.0f, wsc));
        }
    }
    __syncthreads();
    float wscale = s_wsc;

    int g = blockIdx.x * blockDim.x + t;
    if (g >= NGROUP) return;
    int col = g * 4;
    #pragma unroll
    for (int o = 0; o < NOUT; o++) {
        const float* wr = W + o * K_DIM + col;
        int p = 0;
        #pragma unroll
        for (int j = 0; j < 4; j++) {
            int tt = __float2int_rn(__fmul_rn(wr[j], wscale));
            tt = max(-1, min(1, tt));
            p |= (tt & 0xff) << (8 * j);
        }
        g_wpack[g * NOUT + o] = p;
    }
}

// ---------------- main fused kernel ----------------
// dynamic smem (160KB):
//   [0, 64K)      : LUT int[2][256][32]  (pass 2)
//   [64K, 160K)   : W ring  [WARPS][D2][1KB]  (pass 2)
//   [0, 96K)      : pass-1 x ring [WARPS][D1][512B]  (aliases; temporally safe)
extern __shared__ char s_dyn[];

// exact reference rounding: q = rn_half_even(fl(x*s)); no FFMA contraction
#define QIDX(v, sv) \
    (__float_as_int(__fadd_rn(__fmul_rn((v), (sv)), MAGIC)) - 0x4B400000)

#define BODY(a, wA, wB, sv, lp, aL, aH)                                        \
    do {                                                                       \
        int q0 = QIDX((a).x, sv);                                              \
        int q1 = QIDX((a).y, sv);                                              \
        int q2 = QIDX((a).z, sv);                                              \
        int q3 = QIDX((a).w, sv);                                              \
        unsigned R0 = (unsigned)(lp)[q0 << 5];                                 \
        unsigned R1 = (unsigned)(lp)[q1 << 5];                                 \
        unsigned R2 = (unsigned)(lp)[q2 << 5];                                 \
        unsigned R3 = (unsigned)(lp)[q3 << 5];                                 \
        unsigned lo = prmt(R0, R1, 0x5410);                                    \
        unsigned hi = prmt(R2, R3, 0x5410);                                    \
        unsigned hp = prmt(prmt(R0, R1, 0x0062), prmt(R2, R3, 0x0062), 0x5410);\
        aL[0] = dp2a_lo_us(lo, (wA).x, aL[0]); aL[0] = dp2a_hi_us(hi, (wA).x, aL[0]); aH[0] = dp4a_ss(hp, (wA).x, aH[0]); \
        aL[1] = dp2a_lo_us(lo, (wA).y, aL[1]); aL[1] = dp2a_hi_us(hi, (wA).y, aL[1]); aH[1] = dp4a_ss(hp, (wA).y, aH[1]); \
        aL[2] = dp2a_lo_us(lo, (wA).z, aL[2]); aL[2] = dp2a_hi_us(hi, (wA).z, aL[2]); aH[2] = dp4a_ss(hp, (wA).z, aH[2]); \
        aL[3] = dp2a_lo_us(lo, (wA).w, aL[3]); aL[3] = dp2a_hi_us(hi, (wA).w, aL[3]); aH[3] = dp4a_ss(hp, (wA).w, aH[3]); \
        aL[4] = dp2a_lo_us(lo, (wB).x, aL[4]); aL[4] = dp2a_hi_us(hi, (wB).x, aL[4]); aH[4] = dp4a_ss(hp, (wB).x, aH[4]); \
        aL[5] = dp2a_lo_us(lo, (wB).y, aL[5]); aL[5] = dp2a_hi_us(hi, (wB).y, aL[5]); aH[5] = dp4a_ss(hp, (wB).y, aH[5]); \
        aL[6] = dp2a_lo_us(lo, (wB).z, aL[6]); aL[6] = dp2a_hi_us(hi, (wB).z, aL[6]); aH[6] = dp4a_ss(hp, (wB).z, aH[6]); \
        aL[7] = dp2a_lo_us(lo, (wB).w, aL[7]); aL[7] = dp2a_hi_us(hi, (wB).w, aL[7]); aH[7] = dp4a_ss(hp, (wB).w, aH[7]); \
    } while (0)

__global__ void __launch_bounds__(THREADS, 1)
main_kernel(const float* __restrict__ x, float* __restrict__ out) {
    __shared__ float s_wmax[ROWS][WARPS];
    __shared__ float s_scale[ROWS];
    __shared__ int   s_gexp[ROWS];
    __shared__ unsigned long long s_acc[ROWS * NOUT];

    int*  s_lut = (int*)s_dyn;                 // 64KB (pass 2)
    char* s_w2  = s_dyn + 65536;               // 96KB W ring (pass 2)
    char* s_p1  = s_dyn;                       // 96KB x ring (pass 1, aliases)

    const int tid = threadIdx.x;
    const int wid = tid >> 5, lid = tid & 31;
    const int row0 = blockIdx.x * ROWS;
    const int cbase = wid * CPW;               // this warp's first chunk

    const float4* __restrict__ xr0 = (const float4*)(x + (size_t)row0 * K_DIM);
    const float4* __restrict__ xr1 = (const float4*)(x + (size_t)(row0 + 1) * K_DIM);

    // ================= pass 1: per-warp cp.async stream, max|x| =============
    // 50 chunks/warp (25 per row); chunk c: row = c>=25, lane gets 16B
    {
        char* ring = s_p1 + (wid * D1) * 512 + lid * 16;
        #pragma unroll
        for (int d = 0; d < D1; d++) {         // prologue: chunks 0..7 (row 0)
            int g = (cbase + d) * 32 + lid;
            cp_async16(ring + d * 512, &xr0[g]);
            CP_COMMIT();
        }
        float m0 = 0.f, m1 = 0.f;
        for (int c = 0; c < 2 * CPW; c++) {
            CP_WAIT(D1 - 1);
            float4 v = *(float4*)(ring + (c & (D1 - 1)) * 512);
            int cn = c + D1;
            if (cn < 2 * CPW) {
                int r   = (cn >= CPW);
                int idx = cn - (r ? CPW : 0);
                int g   = (cbase + idx) * 32 + lid;
                const float4* src = r ? &xr1[g] : &xr0[g];
                cp_async16(ring + (c & (D1 - 1)) * 512, src);
            }
            CP_COMMIT();
            float mv = fmaxf(fmaxf(fabsf(v.x), fabsf(v.y)),
                             fmaxf(fabsf(v.z), fabsf(v.w)));
            if (c < CPW) m0 = fmaxf(m0, mv); else m1 = fmaxf(m1, mv);
        }
        CP_WAIT(0);                             // drain before smem reuse
        #pragma unroll
        for (int off = 16; off > 0; off >>= 1) {
            m0 = fmaxf(m0, __shfl_xor_sync(0xffffffffu, m0, off));
            m1 = fmaxf(m1, __shfl_xor_sync(0xffffffffu, m1, off));
        }
        if (lid == 0) { s_wmax[0][wid] = m0; s_wmax[1][wid] = m1; }
    }
    if (tid < ROWS * NOUT) s_acc[tid] = 0ull;
    __syncthreads();
    if (tid < ROWS) {
        float m = s_wmax[tid][0];
        #pragma unroll
        for (int i = 1; i < WARPS; i++) m = fmaxf(m, s_wmax[tid][i]);
        s_scale[tid] = __fdiv_rn(127.0f, fmaxf(m, EPS_F));  // == reference
    }
    __syncthreads();
    const float s0 = s_scale[0];
    const float s1 = s_scale[1];

    // ---- build per-row tf32 LUT: R[q] = tf32(fl(q/scale)) / 2^gexp ----
    for (int e = tid; e < 2 * 256; e += THREADS) {
        int r  = e >> 8;
        int qb = e & 255;               // q = qb - 128
        int q  = qb - 128;
        float s = s_scale[r];
        float t1 = tf32_rna(__fdiv_rn(1.0f, s));
        int gexp = ilogbf(t1) - 10;
        int R = 0;
        if (q != -128) {
            float rr = __fdiv_rn((float)q, s);
            float t  = tf32_rna(rr);
            R = __float2int_rn(ldexpf(t, -gexp));
        }
        if (qb == 129) s_gexp[r] = gexp;
        int* dst = s_lut + r * 8192 + qb * 32;
        #pragma unroll
        for (int l = 0; l < 32; l++) dst[l] = R;  // lane-replicated: no conflicts
    }
    __syncthreads();

    // ============ pass 2: W per-warp cp.async ring + x plain LDG =============
    int aL0[NOUT] = {0,0,0,0,0,0,0,0}, aH0[NOUT] = {0,0,0,0,0,0,0,0};
    int aL1[NOUT] = {0,0,0,0,0,0,0,0}, aH1[NOUT] = {0,0,0,0,0,0,0,0};
    const int4* __restrict__ wp = (const int4*)g_wpack;
    const int* __restrict__ lp0 = s_lut + 4096 + lid;          // q=0 centered
    const int* __restrict__ lp1 = s_lut + 8192 + 4096 + lid;

    {
        char* ring = s_w2 + (wid * D2) * 1024 + lid * 16;
        #pragma unroll
        for (int d = 0; d < D2; d++) {         // prologue: W for chunks 0..3
            int g = (cbase + d) * 32 + lid;
            cp_async16(ring + d * 1024,       &wp[2 * g]);
            cp_async16(ring + d * 1024 + 512, &wp[2 * g + 1]);
            CP_COMMIT();
        }
        #pragma unroll 4
        for (int i = 0; i < CPW; i++) {
            CP_WAIT(D2 - 1);
            char* sb = ring + (i & (D2 - 1)) * 1024;
            int4 wA = *(int4*)sb;
            int4 wB = *(int4*)(sb + 512);
            int g = (cbase + i) * 32 + lid;
            float4 a = xr0[g];                 // L2-resident (pass 1)
            float4 b = xr1[g];
            int j = i + D2;
            if (j < CPW) {
                int gj = (cbase + j) * 32 + lid;
                cp_async16(sb,       &wp[2 * gj]);
                cp_async16(sb + 512, &wp[2 * gj + 1]);
            }
            CP_COMMIT();
            BODY(a, wA, wB, s0, lp0, aL0, aH0);
            BODY(b, wA, wB, s1, lp1, aL1, aH1);
        }
        CP_WAIT(0);
    }

    // ---- exact integer reduction ----
    #pragma unroll
    for (int o = 0; o < NOUT; o++) {
        int L0 = __reduce_add_sync(0xffffffffu, aL0[o]);
        int H0 = __reduce_add_sync(0xffffffffu, aH0[o]);
        int L1 = __reduce_add_sync(0xffffffffu, aL1[o]);
        int H1 = __reduce_add_sync(0xffffffffu, aH1[o]);
        if (lid == 0) {
            long long v0 = (long long)H0 * 65536ll + (long long)L0;
            long long v1 = (long long)H1 * 65536ll + (long long)L1;
            atomicAdd(&s_acc[o],        (unsigned long long)v0);
            atomicAdd(&s_acc[NOUT + o], (unsigned long long)v1);
        }
    }
    __syncthreads();

    // ---- softmax (exact tf32-emulated logits) ----
    if (tid < ROWS) {
        float fs = ldexpf(1.0f, s_gexp[tid]);
        float c  = g_c;
        float y[NOUT];
        float mx = -3.0e38f;
        #pragma unroll
        for (int o = 0; o < NOUT; o++) {
            long long S = (long long)s_acc[tid * NOUT + o];
            y[o] = ((float)S * fs) * c;
            mx = fmaxf(mx, y[o]);
        }
        float se = 0.f;
        #pragma unroll
        for (int o = 0; o < NOUT; o++) {
            y[o] = expf(y[o] - mx);
            se += y[o];
        }
        float inv = 1.0f / se;
        #pragma unroll
        for (int o = 0; o < NOUT; o++)
            out[(size_t)(row0 + tid) * NOUT + o] = y[o] * inv;
    }
}

// ---------------- launch ----------------
extern "C" void kernel_launch(void* const* d_in, const int* in_sizes, int n_in,
                              void* d_out, int out_size) {
    const float* x = (const float*)d_in[0];
    const float* W = (const float*)d_in[1];
    if (n_in >= 2 && in_sizes[0] == NOUT * K_DIM && in_sizes[1] == NBATCH * K_DIM) {
        x = (const float*)d_in[1];
        W = (const float*)d_in[0];
    }
    float* out = (float*)d_out;

    const int dyn = 65536 + WARPS * D2 * 1024;   // 160KB -> 1 CTA/SM
    cudaFuncSetAttribute(main_kernel,
                         cudaFuncAttributeMaxDynamicSharedMemorySize, dyn);

    wmean_kernel<<<MEAN_BLKS, 256>>>(W);
    wpack_kernel<<<(NGROUP + 255) / 256, 256>>>(W);
    main_kernel<<<NBATCH / ROWS, THREADS, dyn>>>(x, out);
}

// round 8
// speedup vs baseline: 1.3413x; 1.3413x over previous
#include <cuda_runtime.h>
#include <math.h>

#define K_DIM   76800           // 3*160*160
#define NGROUP  19200           // groups of 4 columns
#define NBATCH  1024
#define NOUT    8
#define THREADS 640             // 20 warps
#define WARPS   20
#define GRID    128             // persistent CTAs
#define PPC     4               // pairs per CTA: 128*4 = 512 pairs = 1024 rows
#define NITER   (NGROUP / THREADS)   // 30 exact
#define EPS_F   1e-5f
#define MAGIC   12582912.0f     // 2^23 + 2^22

// ---------------- device scratch ----------------
#define MEAN_BLKS 512
__device__ float  g_mp[MEAN_BLKS];
__device__ float  g_wscale;               // fl(1/clip(mean|W|,eps))
__device__ float  g_c;                    // tf32(fl(1/g_wscale))
__device__ int    g_wpack[NGROUP * NOUT]; // packed ternary weights (s8 x4)

// ---------------- ptx helpers ----------------
__device__ __forceinline__ float tf32_rna(float x) {
    unsigned u;
    asm("cvt.rna.tf32.f32 %0, %1;" : "=r"(u) : "f"(x));
    return __uint_as_float(u);
}
__device__ __forceinline__ int dp4a_ss(unsigned a, int b, int c) {
    asm("dp4a.s32.s32 %0, %1, %2, %3;" : "=r"(c) : "r"(a), "r"(b), "r"(c));
    return c;
}
__device__ __forceinline__ int dp2a_lo_us(unsigned a, int b, int c) {
    asm("dp2a.lo.u32.s32 %0, %1, %2, %3;" : "=r"(c) : "r"(a), "r"(b), "r"(c));
    return c;
}
__device__ __forceinline__ int dp2a_hi_us(unsigned a, int b, int c) {
    asm("dp2a.hi.u32.s32 %0, %1, %2, %3;" : "=r"(c) : "r"(a), "r"(b), "r"(c));
    return c;
}
__device__ __forceinline__ unsigned prmt(unsigned a, unsigned b, unsigned s) {
    unsigned d;
    asm("prmt.b32 %0, %1, %2, %3;" : "=r"(d) : "r"(a), "r"(b), "r"(s));
    return d;
}

// ---------------- W pipeline (validated R7: 5.6us + ~2.5us) ----------------
__global__ void wmean_kernel(const float* __restrict__ W) {
    const float4* W4 = (const float4*)W;
    const int n4 = NOUT * K_DIM / 4;   // 153600
    float s = 0.f;
    for (int i = blockIdx.x * blockDim.x + threadIdx.x; i < n4;
         i += gridDim.x * blockDim.x) {
        float4 v = W4[i];
        s += ((fabsf(v.x) + fabsf(v.y)) + (fabsf(v.z) + fabsf(v.w)));
    }
    __shared__ float sh[256];
    sh[threadIdx.x] = s;
    __syncthreads();
    for (int off = 128; off > 0; off >>= 1) {
        if (threadIdx.x < off) sh[threadIdx.x] += sh[threadIdx.x + off];
        __syncthreads();
    }
    if (threadIdx.x == 0) g_mp[blockIdx.x] = sh[0];
}

__global__ void wpack_kernel(const float* __restrict__ W) {
    __shared__ double sh[256];
    __shared__ float s_wsc;
    int t = threadIdx.x;
    sh[t] = (double)g_mp[t] + (double)g_mp[t + 256];
    __syncthreads();
    for (int off = 128; off > 0; off >>= 1) {
        if (t < off) sh[t] += sh[t + off];
        __syncthreads();
    }
    if (t == 0) {
        float sumf = (float)sh[0];
        float mean = __fdiv_rn(sumf, (float)(NOUT * K_DIM));
        float mcl  = fmaxf(mean, EPS_F);
        float wsc  = __fdiv_rn(1.0f, mcl);
        s_wsc = wsc;
        if (blockIdx.x == 0) {
            g_wscale = wsc;
            g_c = tf32_rna(__fdiv_rn(1.0f, wsc));
        }
    }
    __syncthreads();
    float wscale = s_wsc;

    int g = blockIdx.x * blockDim.x + t;
    if (g >= NGROUP) return;
    int col = g * 4;
    #pragma unroll
    for (int o = 0; o < NOUT; o++) {
        const float* wr = W + o * K_DIM + col;
        int p = 0;
        #pragma unroll
        for (int j = 0; j < 4; j++) {
            int tt = __float2int_rn(__fmul_rn(wr[j], wscale));
            tt = max(-1, min(1, tt));
            p |= (tt & 0xff) << (8 * j);
        }
        g_wpack[g * NOUT + o] = p;
    }
}

// ---------------- main fused persistent kernel ----------------
extern __shared__ int s_lut[];   // int[2][256][32] = 64KB, lane-replicated

// exact reference rounding: q = rn_half_even(fl(x*s)); no FFMA contraction
#define QIDX(v, sv) \
    (__float_as_int(__fadd_rn(__fmul_rn((v), (sv)), MAGIC)) - 0x4B400000)

#define BODY(a, wA, wB, sv, lp, aL, aH)                                        \
    do {                                                                       \
        int q0 = QIDX((a).x, sv);                                              \
        int q1 = QIDX((a).y, sv);                                              \
        int q2 = QIDX((a).z, sv);                                              \
        int q3 = QIDX((a).w, sv);                                              \
        unsigned R0 = (unsigned)(lp)[q0 << 5];                                 \
        unsigned R1 = (unsigned)(lp)[q1 << 5];                                 \
        unsigned R2 = (unsigned)(lp)[q2 << 5];                                 \
        unsigned R3 = (unsigned)(lp)[q3 << 5];                                 \
        unsigned lo = prmt(R0, R1, 0x5410);                                    \
        unsigned hi = prmt(R2, R3, 0x5410);                                    \
        unsigned hp = prmt(prmt(R0, R1, 0x0062), prmt(R2, R3, 0x0062), 0x5410);\
        aL[0] = dp2a_lo_us(lo, (wA).x, aL[0]); aL[0] = dp2a_hi_us(hi, (wA).x, aL[0]); aH[0] = dp4a_ss(hp, (wA).x, aH[0]); \
        aL[1] = dp2a_lo_us(lo, (wA).y, aL[1]); aL[1] = dp2a_hi_us(hi, (wA).y, aL[1]); aH[1] = dp4a_ss(hp, (wA).y, aH[1]); \
        aL[2] = dp2a_lo_us(lo, (wA).z, aL[2]); aL[2] = dp2a_hi_us(hi, (wA).z, aL[2]); aH[2] = dp4a_ss(hp, (wA).z, aH[2]); \
        aL[3] = dp2a_lo_us(lo, (wA).w, aL[3]); aL[3] = dp2a_hi_us(hi, (wA).w, aL[3]); aH[3] = dp4a_ss(hp, (wA).w, aH[3]); \
        aL[4] = dp2a_lo_us(lo, (wB).x, aL[4]); aL[4] = dp2a_hi_us(hi, (wB).x, aL[4]); aH[4] = dp4a_ss(hp, (wB).x, aH[4]); \
        aL[5] = dp2a_lo_us(lo, (wB).y, aL[5]); aL[5] = dp2a_hi_us(hi, (wB).y, aL[5]); aH[5] = dp4a_ss(hp, (wB).y, aH[5]); \
        aL[6] = dp2a_lo_us(lo, (wB).z, aL[6]); aL[6] = dp2a_hi_us(hi, (wB).z, aL[6]); aH[6] = dp4a_ss(hp, (wB).z, aH[6]); \
        aL[7] = dp2a_lo_us(lo, (wB).w, aL[7]); aL[7] = dp2a_hi_us(hi, (wB).w, aL[7]); aH[7] = dp4a_ss(hp, (wB).w, aH[7]); \
    } while (0)

__global__ void __launch_bounds__(THREADS, 1)
main_kernel(const float* __restrict__ x, float* __restrict__ out) {
    __shared__ float s_wmax[2][WARPS];
    __shared__ float s_scale[2];
    __shared__ int   s_gexp[2];
    __shared__ unsigned long long s_acc[2 * NOUT];

    const int tid = threadIdx.x;
    const int wid = tid >> 5, lid = tid & 31;
    const int p0 = blockIdx.x * PPC;           // first pair owned by this CTA
    const int4* __restrict__ wp = (const int4*)g_wpack;

    // ---- prologue: pass 1 (max|x|) for pair p0, plain R2-style loop ----
    {
        const float4* __restrict__ xa = (const float4*)(x + (size_t)(2 * p0) * K_DIM);
        const float4* __restrict__ xb = (const float4*)(x + (size_t)(2 * p0 + 1) * K_DIM);
        float m0 = 0.f, m1 = 0.f;
        #pragma unroll 5
        for (int g = tid; g < NGROUP; g += THREADS) {
            float4 a = xa[g];
            float4 b = xb[g];
            m0 = fmaxf(m0, fmaxf(fmaxf(fabsf(a.x), fabsf(a.y)),
                                 fmaxf(fabsf(a.z), fabsf(a.w))));
            m1 = fmaxf(m1, fmaxf(fmaxf(fabsf(b.x), fabsf(b.y)),
                                 fmaxf(fabsf(b.z), fabsf(b.w))));
        }
        #pragma unroll
        for (int off = 16; off > 0; off >>= 1) {
            m0 = fmaxf(m0, __shfl_xor_sync(0xffffffffu, m0, off));
            m1 = fmaxf(m1, __shfl_xor_sync(0xffffffffu, m1, off));
        }
        if (lid == 0) { s_wmax[0][wid] = m0; s_wmax[1][wid] = m1; }
    }

    // ---- stage loop: pass2(pair p) fused with pass1(pair p+1) ----
    for (int s = 0; s < PPC; s++) {
        const int p = p0 + s;
        const bool do1 = (s + 1 < PPC);
        const float4* __restrict__ xr0 = (const float4*)(x + (size_t)(2 * p) * K_DIM);
        const float4* __restrict__ xr1 = (const float4*)(x + (size_t)(2 * p + 1) * K_DIM);
        const float4* __restrict__ xr2 = (const float4*)(x + (size_t)(2 * p + 2) * K_DIM);
        const float4* __restrict__ xr3 = (const float4*)(x + (size_t)(2 * p + 3) * K_DIM);

        __syncthreads();                    // s_wmax ready; old LUT users done
        if (tid < 2) {
            float m = s_wmax[tid][0];
            #pragma unroll
            for (int i = 1; i < WARPS; i++) m = fmaxf(m, s_wmax[tid][i]);
            s_scale[tid] = __fdiv_rn(127.0f, fmaxf(m, EPS_F));  // == reference
        }
        if (tid < 2 * NOUT) s_acc[tid] = 0ull;
        __syncthreads();

        // build per-row tf32 LUT: R[q] = tf32(fl(q/scale)) / 2^gexp (exact int)
        for (int e = tid; e < 2 * 256; e += THREADS) {
            int r  = e >> 8;
            int qb = e & 255;               // q = qb - 128
            int q  = qb - 128;
            float sc = s_scale[r];
            float t1 = tf32_rna(__fdiv_rn(1.0f, sc));
            int gexp = ilogbf(t1) - 10;
            int R = 0;
            if (q != -128) {
                float rr = __fdiv_rn((float)q, sc);
                float t  = tf32_rna(rr);
                R = __float2int_rn(ldexpf(t, -gexp));
            }
            if (qb == 129) s_gexp[r] = gexp;
            int* dst = s_lut + r * 8192 + qb * 32;
            #pragma unroll
            for (int l = 0; l < 32; l++) dst[l] = R;   // lane-replicated
        }
        __syncthreads();
        const float s0 = s_scale[0];
        const float s1 = s_scale[1];
        const int* __restrict__ lp0 = s_lut + 4096 + lid;
        const int* __restrict__ lp1 = s_lut + 8192 + 4096 + lid;

        int aL0[NOUT] = {0,0,0,0,0,0,0,0}, aH0[NOUT] = {0,0,0,0,0,0,0,0};
        int aL1[NOUT] = {0,0,0,0,0,0,0,0}, aH1[NOUT] = {0,0,0,0,0,0,0,0};
        float m0 = 0.f, m1 = 0.f;

        #pragma unroll 2
        for (int i = 0; i < NITER; i++) {
            const int g = tid + i * THREADS;
            // pass-1 loads for NEXT pair (DRAM) issued first, consumed last:
            // ~100 intervening instructions give natural latency cover.
            float4 c, d;
            if (do1) { c = xr2[g]; d = xr3[g]; }
            // pass-2: current pair (x L2-resident from previous stage)
            float4 a = xr0[g];
            float4 b = xr1[g];
            int4 wA = wp[2 * g];
            int4 wB = wp[2 * g + 1];
            BODY(a, wA, wB, s0, lp0, aL0, aH0);
            BODY(b, wA, wB, s1, lp1, aL1, aH1);
            if (do1) {
                m0 = fmaxf(m0, fmaxf(fmaxf(fabsf(c.x), fabsf(c.y)),
                                     fmaxf(fabsf(c.z), fabsf(c.w))));
                m1 = fmaxf(m1, fmaxf(fmaxf(fabsf(d.x), fabsf(d.y)),
                                     fmaxf(fabsf(d.z), fabsf(d.w))));
            }
        }

        // exact integer reduction for pair p
        #pragma unroll
        for (int o = 0; o < NOUT; o++) {
            int L0 = __reduce_add_sync(0xffffffffu, aL0[o]);
            int H0 = __reduce_add_sync(0xffffffffu, aH0[o]);
            int L1 = __reduce_add_sync(0xffffffffu, aL1[o]);
            int H1 = __reduce_add_sync(0xffffffffu, aH1[o]);
            if (lid == 0) {
                long long v0 = (long long)H0 * 65536ll + (long long)L0;
                long long v1 = (long long)H1 * 65536ll + (long long)L1;
                atomicAdd(&s_acc[o],        (unsigned long long)v0);
                atomicAdd(&s_acc[NOUT + o], (unsigned long long)v1);
            }
        }
        // publish next pair's maxes
        if (do1) {
            #pragma unroll
            for (int off = 16; off > 0; off >>= 1) {
                m0 = fmaxf(m0, __shfl_xor_sync(0xffffffffu, m0, off));
                m1 = fmaxf(m1, __shfl_xor_sync(0xffffffffu, m1, off));
            }
            if (lid == 0) { s_wmax[0][wid] = m0; s_wmax[1][wid] = m1; }
        }
        __syncthreads();

        // softmax + write rows of pair p (exact tf32-emulated logits)
        if (tid < 2) {
            float fs = ldexpf(1.0f, s_gexp[tid]);
            float cc = g_c;
            float y[NOUT];
            float mx = -3.0e38f;
            #pragma unroll
            for (int o = 0; o < NOUT; o++) {
                long long S = (long long)s_acc[tid * NOUT + o];
                y[o] = ((float)S * fs) * cc;
                mx = fmaxf(mx, y[o]);
            }
            float se = 0.f;
            #pragma unroll
            for (int o = 0; o < NOUT; o++) {
                y[o] = expf(y[o] - mx);
                se += y[o];
            }
            float inv = 1.0f / se;
            #pragma unroll
            for (int o = 0; o < NOUT; o++)
                out[(size_t)(2 * p + tid) * NOUT + o] = y[o] * inv;
        }
    }
}

// ---------------- launch ----------------
extern "C" void kernel_launch(void* const* d_in, const int* in_sizes, int n_in,
                              void* d_out, int out_size) {
    const float* x = (const float*)d_in[0];
    const float* W = (const float*)d_in[1];
    if (n_in >= 2 && in_sizes[0] == NOUT * K_DIM && in_sizes[1] == NBATCH * K_DIM) {
        x = (const float*)d_in[1];
        W = (const float*)d_in[0];
    }
    float* out = (float*)d_out;

    cudaFuncSetAttribute(main_kernel,
                         cudaFuncAttributeMaxDynamicSharedMemorySize, 66 * 1024);
    cudaFuncSetAttribute(main_kernel,
                         cudaFuncAttributePreferredSharedMemoryCarveout, 33);

    wmean_kernel<<<MEAN_BLKS, 256>>>(W);
    wpack_kernel<<<(NGROUP + 255) / 256, 256>>>(W);
    main_kernel<<<GRID, THREADS, 64 * 1024>>>(x, out);
}

// round 9
// speedup vs baseline: 1.3758x; 1.0257x over previous
#include <cuda_runtime.h>
#include <math.h>

#define K_DIM   76800           // 3*160*160
#define NGROUP  19200           // groups of 4 columns
#define NBATCH  1024
#define NOUT    8
#define THREADS 768
#define WARPS   24
#define ROWS    2
#define NITER   (NGROUP / THREADS)   // 25
#define EPS_F   1e-5f
#define MAGIC   12582912.0f     // 2^23 + 2^22

// ---------------- device scratch ----------------
#define MEAN_BLKS 512
__device__ float  g_mp[MEAN_BLKS];
__device__ float  g_wscale;               // fl(1/clip(mean|W|,eps))
__device__ float  g_c;                    // tf32(fl(1/g_wscale))
__device__ int    g_wpack[NGROUP * NOUT]; // packed ternary weights (s8 x4)

// ---------------- ptx helpers ----------------
__device__ __forceinline__ float tf32_rna(float x) {
    unsigned u;
    asm("cvt.rna.tf32.f32 %0, %1;" : "=r"(u) : "f"(x));
    return __uint_as_float(u);
}
__device__ __forceinline__ int dp4a_ss(unsigned a, int b, int c) {
    asm("dp4a.s32.s32 %0, %1, %2, %3;" : "=r"(c) : "r"(a), "r"(b), "r"(c));
    return c;
}
__device__ __forceinline__ int dp2a_lo_us(unsigned a, int b, int c) {
    asm("dp2a.lo.u32.s32 %0, %1, %2, %3;" : "=r"(c) : "r"(a), "r"(b), "r"(c));
    return c;
}
__device__ __forceinline__ int dp2a_hi_us(unsigned a, int b, int c) {
    asm("dp2a.hi.u32.s32 %0, %1, %2, %3;" : "=r"(c) : "r"(a), "r"(b), "r"(c));
    return c;
}
__device__ __forceinline__ unsigned prmt(unsigned a, unsigned b, unsigned s) {
    unsigned d;
    asm("prmt.b32 %0, %1, %2, %3;" : "=r"(d) : "r"(a), "r"(b), "r"(s));
    return d;
}

// ---------------- W pipeline (validated: ~5.6us + ~2.5us) ----------------
__global__ void wmean_kernel(const float* __restrict__ W) {
    const float4* W4 = (const float4*)W;
    const int n4 = NOUT * K_DIM / 4;   // 153600
    float s = 0.f;
    for (int i = blockIdx.x * blockDim.x + threadIdx.x; i < n4;
         i += gridDim.x * blockDim.x) {
        float4 v = W4[i];
        s += ((fabsf(v.x) + fabsf(v.y)) + (fabsf(v.z) + fabsf(v.w)));
    }
    __shared__ float sh[256];
    sh[threadIdx.x] = s;
    __syncthreads();
    for (int off = 128; off > 0; off >>= 1) {
        if (threadIdx.x < off) sh[threadIdx.x] += sh[threadIdx.x + off];
        __syncthreads();
    }
    if (threadIdx.x == 0) g_mp[blockIdx.x] = sh[0];
}

__global__ void wpack_kernel(const float* __restrict__ W) {
    __shared__ double sh[256];
    __shared__ float s_wsc;
    int t = threadIdx.x;
    sh[t] = (double)g_mp[t] + (double)g_mp[t + 256];
    __syncthreads();
    for (int off = 128; off > 0; off >>= 1) {
        if (t < off) sh[t] += sh[t + off];
        __syncthreads();
    }
    if (t == 0) {
        float sumf = (float)sh[0];
        float mean = __fdiv_rn(sumf, (float)(NOUT * K_DIM));
        float mcl  = fmaxf(mean, EPS_F);
        float wsc  = __fdiv_rn(1.0f, mcl);
        s_wsc = wsc;
        if (blockIdx.x == 0) {
            g_wscale = wsc;
            g_c = tf32_rna(__fdiv_rn(1.0f, wsc));
        }
    }
    __syncthreads();
    float wscale = s_wsc;

    int g = blockIdx.x * blockDim.x + t;
    if (g >= NGROUP) return;
    int col = g * 4;
    #pragma unroll
    for (int o = 0; o < NOUT; o++) {
        const float* wr = W + o * K_DIM + col;
        int p = 0;
        #pragma unroll
        for (int j = 0; j < 4; j++) {
            int tt = __float2int_rn(__fmul_rn(wr[j], wscale));
            tt = max(-1, min(1, tt));
            p |= (tt & 0xff) << (8 * j);
        }
        g_wpack[g * NOUT + o] = p;
    }
}

// ---------------- main fused kernel (R2 structure + phase rotation) --------
extern __shared__ int s_lut[];   // int[2][256][32] = 64KB, lane-replicated

// exact reference rounding: q = rn_half_even(fl(x*s)); no FFMA contraction
#define QIDX(v, sv) \
    (__float_as_int(__fadd_rn(__fmul_rn((v), (sv)), MAGIC)) - 0x4B400000)

#define BODY(a, wA, wB, sv, lp, aL, aH)                                        \
    do {                                                                       \
        int q0 = QIDX((a).x, sv);                                              \
        int q1 = QIDX((a).y, sv);                                              \
        int q2 = QIDX((a).z, sv);                                              \
        int q3 = QIDX((a).w, sv);                                              \
        unsigned R0 = (unsigned)(lp)[q0 << 5];                                 \
        unsigned R1 = (unsigned)(lp)[q1 << 5];                                 \
        unsigned R2 = (unsigned)(lp)[q2 << 5];                                 \
        unsigned R3 = (unsigned)(lp)[q3 << 5];                                 \
        unsigned lo = prmt(R0, R1, 0x5410);                                    \
        unsigned hi = prmt(R2, R3, 0x5410);                                    \
        unsigned hp = prmt(prmt(R0, R1, 0x0062), prmt(R2, R3, 0x0062), 0x5410);\
        aL[0] = dp2a_lo_us(lo, (wA).x, aL[0]); aL[0] = dp2a_hi_us(hi, (wA).x, aL[0]); aH[0] = dp4a_ss(hp, (wA).x, aH[0]); \
        aL[1] = dp2a_lo_us(lo, (wA).y, aL[1]); aL[1] = dp2a_hi_us(hi, (wA).y, aL[1]); aH[1] = dp4a_ss(hp, (wA).y, aH[1]); \
        aL[2] = dp2a_lo_us(lo, (wA).z, aL[2]); aL[2] = dp2a_hi_us(hi, (wA).z, aL[2]); aH[2] = dp4a_ss(hp, (wA).z, aH[2]); \
        aL[3] = dp2a_lo_us(lo, (wA).w, aL[3]); aL[3] = dp2a_hi_us(hi, (wA).w, aL[3]); aH[3] = dp4a_ss(hp, (wA).w, aH[3]); \
        aL[4] = dp2a_lo_us(lo, (wB).x, aL[4]); aL[4] = dp2a_hi_us(hi, (wB).x, aL[4]); aH[4] = dp4a_ss(hp, (wB).x, aH[4]); \
        aL[5] = dp2a_lo_us(lo, (wB).y, aL[5]); aL[5] = dp2a_hi_us(hi, (wB).y, aL[5]); aH[5] = dp4a_ss(hp, (wB).y, aH[5]); \
        aL[6] = dp2a_lo_us(lo, (wB).z, aL[6]); aL[6] = dp2a_hi_us(hi, (wB).z, aL[6]); aH[6] = dp4a_ss(hp, (wB).z, aH[6]); \
        aL[7] = dp2a_lo_us(lo, (wB).w, aL[7]); aL[7] = dp2a_hi_us(hi, (wB).w, aL[7]); aH[7] = dp4a_ss(hp, (wB).w, aH[7]); \
    } while (0)

__global__ void __launch_bounds__(THREADS, 1)
main_kernel(const float* __restrict__ x, float* __restrict__ out) {
    __shared__ float s_wmax[ROWS][WARPS];
    __shared__ float s_scale[ROWS];
    __shared__ int   s_gexp[ROWS];
    __shared__ unsigned long long s_acc[ROWS * NOUT];

    const int tid = threadIdx.x;
    const int wid = tid >> 5, lid = tid & 31;
    const int row0 = blockIdx.x * ROWS;
    // phase rotation: warp w starts its sweep at chunk (w % NITER)
    const int i0 = wid % NITER;

    const float4* __restrict__ xr0 = (const float4*)(x + (size_t)row0 * K_DIM);
    const float4* __restrict__ xr1 = (const float4*)(x + (size_t)(row0 + 1) * K_DIM);

    // ---- pass 1: per-row max |x|, warp-phase-rotated (order-free) ----
    float m0 = 0.f, m1 = 0.f;
    #pragma unroll 5
    for (int i = i0; i < NITER; i++) {
        int g = tid + i * THREADS;
        float4 a = xr0[g];
        float4 b = xr1[g];
        m0 = fmaxf(m0, fmaxf(fmaxf(fabsf(a.x), fabsf(a.y)),
                             fmaxf(fabsf(a.z), fabsf(a.w))));
        m1 = fmaxf(m1, fmaxf(fmaxf(fabsf(b.x), fabsf(b.y)),
                             fmaxf(fabsf(b.z), fabsf(b.w))));
    }
    #pragma unroll 5
    for (int i = 0; i < i0; i++) {
        int g = tid + i * THREADS;
        float4 a = xr0[g];
        float4 b = xr1[g];
        m0 = fmaxf(m0, fmaxf(fmaxf(fabsf(a.x), fabsf(a.y)),
                             fmaxf(fabsf(a.z), fabsf(a.w))));
        m1 = fmaxf(m1, fmaxf(fmaxf(fabsf(b.x), fabsf(b.y)),
                             fmaxf(fabsf(b.z), fabsf(b.w))));
    }
    #pragma unroll
    for (int off = 16; off > 0; off >>= 1) {
        m0 = fmaxf(m0, __shfl_xor_sync(0xffffffffu, m0, off));
        m1 = fmaxf(m1, __shfl_xor_sync(0xffffffffu, m1, off));
    }
    if (lid == 0) { s_wmax[0][wid] = m0; s_wmax[1][wid] = m1; }
    if (tid < ROWS * NOUT) s_acc[tid] = 0ull;
    __syncthreads();
    if (tid < ROWS) {
        float m = s_wmax[tid][0];
        #pragma unroll
        for (int i = 1; i < WARPS; i++) m = fmaxf(m, s_wmax[tid][i]);
        s_scale[tid] = __fdiv_rn(127.0f, fmaxf(m, EPS_F));  // == reference
    }
    __syncthreads();
    const float s0 = s_scale[0];
    const float s1 = s_scale[1];

    // ---- build per-row tf32 LUT: R[q] = tf32(fl(q/scale)) / 2^gexp ----
    for (int e = tid; e < 2 * 256; e += THREADS) {
        int r  = e >> 8;
        int qb = e & 255;               // q = qb - 128
        int q  = qb - 128;
        float s = s_scale[r];
        float t1 = tf32_rna(__fdiv_rn(1.0f, s));
        int gexp = ilogbf(t1) - 10;
        int R = 0;
        if (q != -128) {
            float rr = __fdiv_rn((float)q, s);
            float t  = tf32_rna(rr);
            R = __float2int_rn(ldexpf(t, -gexp));
        }
        if (qb == 129) s_gexp[r] = gexp;
        int* dst = s_lut + r * 8192 + qb * 32;
        #pragma unroll
        for (int l = 0; l < 32; l++) dst[l] = R;  // lane-replicated: no conflicts
    }
    __syncthreads();

    // ---- pass 2: plain loop, warp-phase-rotated (integer sum: order-free) ----
    int aL0[NOUT] = {0,0,0,0,0,0,0,0}, aH0[NOUT] = {0,0,0,0,0,0,0,0};
    int aL1[NOUT] = {0,0,0,0,0,0,0,0}, aH1[NOUT] = {0,0,0,0,0,0,0,0};
    const int4* __restrict__ wp = (const int4*)g_wpack;
    const int* __restrict__ lp0 = s_lut + 4096 + lid;          // q=0 centered
    const int* __restrict__ lp1 = s_lut + 8192 + 4096 + lid;

    #pragma unroll 5
    for (int i = i0; i < NITER; i++) {
        int g = tid + i * THREADS;
        float4 a = xr0[g];
        float4 b = xr1[g];
        int4 wA = wp[2 * g];
        int4 wB = wp[2 * g + 1];
        BODY(a, wA, wB, s0, lp0, aL0, aH0);
        BODY(b, wA, wB, s1, lp1, aL1, aH1);
    }
    #pragma unroll 5
    for (int i = 0; i < i0; i++) {
        int g = tid + i * THREADS;
        float4 a = xr0[g];
        float4 b = xr1[g];
        int4 wA = wp[2 * g];
        int4 wB = wp[2 * g + 1];
        BODY(a, wA, wB, s0, lp0, aL0, aH0);
        BODY(b, wA, wB, s1, lp1, aL1, aH1);
    }

    // ---- exact integer reduction ----
    #pragma unroll
    for (int o = 0; o < NOUT; o++) {
        int L0 = __reduce_add_sync(0xffffffffu, aL0[o]);
        int H0 = __reduce_add_sync(0xffffffffu, aH0[o]);
        int L1 = __reduce_add_sync(0xffffffffu, aL1[o]);
        int H1 = __reduce_add_sync(0xffffffffu, aH1[o]);
        if (lid == 0) {
            long long v0 = (long long)H0 * 65536ll + (long long)L0;
            long long v1 = (long long)H1 * 65536ll + (long long)L1;
            atomicAdd(&s_acc[o],        (unsigned long long)v0);
            atomicAdd(&s_acc[NOUT + o], (unsigned long long)v1);
        }
    }
    __syncthreads();

    // ---- softmax (exact tf32-emulated logits) ----
    if (tid < ROWS) {
        float fs = ldexpf(1.0f, s_gexp[tid]);
        float c  = g_c;
        float y[NOUT];
        float mx = -3.0e38f;
        #pragma unroll
        for (int o = 0; o < NOUT; o++) {
            long long S = (long long)s_acc[tid * NOUT + o];
            y[o] = ((float)S * fs) * c;
            mx = fmaxf(mx, y[o]);
        }
        float se = 0.f;
        #pragma unroll
        for (int o = 0; o < NOUT; o++) {
            y[o] = expf(y[o] - mx);
            se += y[o];
        }
        float inv = 1.0f / se;
        #pragma unroll
        for (int o = 0; o < NOUT; o++)
            out[(size_t)(row0 + tid) * NOUT + o] = y[o] * inv;
    }
}

// ---------------- launch ----------------
extern "C" void kernel_launch(void* const* d_in, const int* in_sizes, int n_in,
                              void* d_out, int out_size) {
    const float* x = (const float*)d_in[0];
    const float* W = (const float*)d_in[1];
    if (n_in >= 2 && in_sizes[0] == NOUT * K_DIM && in_sizes[1] == NBATCH * K_DIM) {
        x = (const float*)d_in[1];
        W = (const float*)d_in[0];
    }
    float* out = (float*)d_out;

    cudaFuncSetAttribute(main_kernel,
                         cudaFuncAttributeMaxDynamicSharedMemorySize, 66 * 1024);
    cudaFuncSetAttribute(main_kernel,
                         cudaFuncAttributePreferredSharedMemoryCarveout, 33);

    wmean_kernel<<<MEAN_BLKS, 256>>>(W);
    wpack_kernel<<<NGROUP / 256, 256>>>(W);
    main_kernel<<<NBATCH / ROWS, THREADS, 64 * 1024>>>(x, out);
}